// round 1
// baseline (speedup 1.0000x reference)
#include <cuda_runtime.h>

#define BATCH 64
#define SEQ   512
#define DIM   300
#define HID   600
#define G4    2400            // 4*HID
#define ROWS  (BATCH*SEQ)     // 32768

// ---------------- scratch (static __device__ allocations, allowed) ----------------
__device__ float g_xw[(size_t)2 * ROWS * G4];   // xw[dir][row][gatecol], 629 MB
__device__ float g_UT[2 * G4 * HID];            // U^T per dir: [n][k]
__device__ float g_h[2][2 * BATCH * HID];       // [parity][dir*B*H + b*H + j]
__device__ float g_c[2 * BATCH * HID];
__device__ float g_hsum[2 * BATCH * HID];

// ---------------- init: zero states ----------------
__global__ void k_init() {
    int i = blockIdx.x * blockDim.x + threadIdx.x;
    if (i < 2 * BATCH * HID) {
        g_h[0][i] = 0.f; g_h[1][i] = 0.f;
        g_c[i] = 0.f; g_hsum[i] = 0.f;
    }
}

// ---------------- transpose U -> UT (coalesced read) ----------------
__global__ void k_transpose(const float* __restrict__ Uf, const float* __restrict__ Ub) {
    int i = blockIdx.x * blockDim.x + threadIdx.x;   // over HID*G4
    if (i >= HID * G4) return;
    int k = i / G4, n = i % G4;
    g_UT[n * HID + k]            = Uf[i];
    g_UT[G4 * HID + n * HID + k] = Ub[i];
}

// ---------------- input GEMM: xw = X @ W + b,  per dir ----------------
// C tile 64x64, BK=12 (300 = 25*12), 256 threads, 4x4 per thread.
#define GBK 12
__global__ void k_gemm(const float* __restrict__ X,
                       const float* __restrict__ Wf, const float* __restrict__ bf,
                       const float* __restrict__ Wb, const float* __restrict__ bb) {
    int dir = blockIdx.z;
    const float* W    = dir ? Wb : Wf;
    const float* bias = dir ? bb : bf;
    int m0 = blockIdx.y * 64;
    int n0 = blockIdx.x * 64;
    __shared__ __align__(16) float As[GBK][64];
    __shared__ __align__(16) float Bs[GBK][64];
    int tid = threadIdx.x;
    int tx = tid & 15, ty = tid >> 4;
    float acc[4][4] = {};
    for (int k0 = 0; k0 < DIM; k0 += GBK) {
        #pragma unroll
        for (int l = 0; l < (64 * GBK) / 256; ++l) {     // 3
            int idx = tid + l * 256;
            int r = idx / GBK, kk = idx % GBK;
            As[kk][r] = X[(size_t)(m0 + r) * DIM + k0 + kk];
        }
        #pragma unroll
        for (int l = 0; l < (64 * GBK) / 256; ++l) {     // 3
            int idx = tid + l * 256;
            int kk = idx / 64, c = idx & 63;
            int col = n0 + c;
            Bs[kk][c] = (col < G4) ? W[(size_t)(k0 + kk) * G4 + col] : 0.f;
        }
        __syncthreads();
        #pragma unroll
        for (int kk = 0; kk < GBK; ++kk) {
            float4 a = *(const float4*)&As[kk][ty * 4];
            float4 b = *(const float4*)&Bs[kk][tx * 4];
            float av[4] = {a.x, a.y, a.z, a.w};
            float bv[4] = {b.x, b.y, b.z, b.w};
            #pragma unroll
            for (int i = 0; i < 4; i++)
                #pragma unroll
                for (int j = 0; j < 4; j++)
                    acc[i][j] += av[i] * bv[j];
        }
        __syncthreads();
    }
    float* outp = g_xw + (size_t)dir * ROWS * G4;
    #pragma unroll
    for (int i = 0; i < 4; i++) {
        int row = m0 + ty * 4 + i;
        #pragma unroll
        for (int j = 0; j < 4; j++) {
            int col = n0 + tx * 4 + j;
            if (col < G4) outp[(size_t)row * G4 + col] = acc[i][j] + bias[col];
        }
    }
}

// ---------------- one recurrent step, both directions ----------------
// Block: dir = blockIdx.y, 8 j-columns (all 4 gates) x all 64 batches.
// z[b, g*600+j] = xw[...] + dot(h[b,:], UT[g*600+j, :])
// Double-buffered smem + register prefetch to hide L2 latency at 1 block/SM.
#define KT 24
#define JT 8
__global__ __launch_bounds__(256, 2) void k_step(const int* __restrict__ lengths, int step) {
    int dir = blockIdx.y;
    int j0  = blockIdx.x * JT;
    __shared__ __align__(16) float h_sh[2][KT][64];
    __shared__ __align__(16) float u_sh[2][KT][32];
    __shared__ float z_sh[64][32];
    int tid = threadIdx.x;
    int rp = step & 1;
    const float* hread  = g_h[rp]     + dir * BATCH * HID;
    float*       hwrite = g_h[rp ^ 1] + dir * BATCH * HID;
    const float* UT = g_UT + dir * G4 * HID;

    int cg = tid & 7, bg = tid >> 3;      // cg: 8 col-groups of 4, bg: 32 b-groups of 2
    int b0 = bg * 2, c0 = cg * 4;

    float ph[6], pu[3];
    // prefetch k0 = 0
    #pragma unroll
    for (int l = 0; l < 6; ++l) {
        int idx = tid + l * 256; int b = idx / KT, kk = idx % KT;
        ph[l] = hread[b * HID + kk];
    }
    #pragma unroll
    for (int l = 0; l < 3; ++l) {
        int idx = tid + l * 256; int c = idx / KT, kk = idx % KT;
        int ucol = (c >> 3) * HID + j0 + (c & 7);
        pu[l] = UT[ucol * HID + kk];
    }
    #pragma unroll
    for (int l = 0; l < 6; ++l) { int idx = tid + l * 256; h_sh[0][idx % KT][idx / KT] = ph[l]; }
    #pragma unroll
    for (int l = 0; l < 3; ++l) { int idx = tid + l * 256; u_sh[0][idx % KT][idx / KT] = pu[l]; }
    __syncthreads();

    float acc[2][4] = {};
    int cur = 0;
    for (int k0 = 0; k0 < HID; k0 += KT) {
        int nk = k0 + KT;
        bool has_next = (nk < HID);
        if (has_next) {   // issue next tile's LDGs early
            #pragma unroll
            for (int l = 0; l < 6; ++l) {
                int idx = tid + l * 256; int b = idx / KT, kk = idx % KT;
                ph[l] = hread[b * HID + nk + kk];
            }
            #pragma unroll
            for (int l = 0; l < 3; ++l) {
                int idx = tid + l * 256; int c = idx / KT, kk = idx % KT;
                int ucol = (c >> 3) * HID + j0 + (c & 7);
                pu[l] = UT[ucol * HID + nk + kk];
            }
        }
        #pragma unroll
        for (int kk = 0; kk < KT; ++kk) {
            float2 h2 = *(const float2*)&h_sh[cur][kk][b0];
            float4 u4 = *(const float4*)&u_sh[cur][kk][c0];
            float uv[4] = {u4.x, u4.y, u4.z, u4.w};
            #pragma unroll
            for (int j = 0; j < 4; j++) {
                acc[0][j] += h2.x * uv[j];
                acc[1][j] += h2.y * uv[j];
            }
        }
        if (has_next) {
            int nb = cur ^ 1;
            #pragma unroll
            for (int l = 0; l < 6; ++l) { int idx = tid + l * 256; h_sh[nb][idx % KT][idx / KT] = ph[l]; }
            #pragma unroll
            for (int l = 0; l < 3; ++l) { int idx = tid + l * 256; u_sh[nb][idx % KT][idx / KT] = pu[l]; }
        }
        __syncthreads();
        cur ^= 1;
    }

    // stage z into shared so one thread can gather all 4 gates of a (b, j)
    #pragma unroll
    for (int j = 0; j < 4; j++) {
        z_sh[b0][c0 + j]     = acc[0][j];
        z_sh[b0 + 1][c0 + j] = acc[1][j];
    }
    __syncthreads();

    // gate math + state update + masked accumulation
    #pragma unroll
    for (int it = 0; it < 2; ++it) {
        int cell = tid + it * 256;          // 512 cells = 64 b x 8 j
        int b = cell >> 3, jj = cell & 7;
        int j = j0 + jj;
        int L = lengths[b];
        int trow; bool active;
        if (dir == 0) { trow = step; active = true; }
        else          { active = (step < L); trow = active ? (L - 1 - step) : 0; }
        if (active) {
            const float* xw = g_xw + ((size_t)dir * ROWS + b * SEQ + trow) * G4;
            float zi = z_sh[b][jj]      + xw[j];
            float zf = z_sh[b][8 + jj]  + xw[HID + j];
            float zg = z_sh[b][16 + jj] + xw[2 * HID + j];
            float zo = z_sh[b][24 + jj] + xw[3 * HID + j];
            float ig = 1.f / (1.f + __expf(-zi));
            float fg = 1.f / (1.f + __expf(-zf));
            float gg = tanhf(zg);
            float og = 1.f / (1.f + __expf(-zo));
            int sidx = dir * BATCH * HID + b * HID + j;
            float cn = fg * g_c[sidx] + ig * gg;
            g_c[sidx] = cn;
            float h = og * tanhf(cn);
            hwrite[b * HID + j] = h;
            bool accum = (dir == 0) ? (step < L) : true;
            if (accum) g_hsum[sidx] += h;
        }
    }
}

// ---------------- finalize: mean over T ----------------
__global__ void k_final(float* __restrict__ out) {
    int i = blockIdx.x * blockDim.x + threadIdx.x;
    if (i >= BATCH * 2 * HID) return;
    int b = i / (2 * HID), j = i % (2 * HID);
    float v = (j < HID) ? g_hsum[b * HID + j]
                        : g_hsum[BATCH * HID + b * HID + (j - HID)];
    out[i] = v * (1.0f / SEQ);
}

// ---------------- launch ----------------
extern "C" void kernel_launch(void* const* d_in, const int* in_sizes, int n_in,
                              void* d_out, int out_size) {
    const float *X = nullptr, *Wf = nullptr, *Uf = nullptr, *bf = nullptr;
    const float *Wb = nullptr, *Ub = nullptr, *bb = nullptr;
    const int* lengths = nullptr;
    int cW = 0, cU = 0, cb = 0;
    for (int i = 0; i < n_in; i++) {
        int s = in_sizes[i];
        if      (s == BATCH * SEQ * DIM) X = (const float*)d_in[i];
        else if (s == BATCH)             lengths = (const int*)d_in[i];
        else if (s == DIM * G4)   { if (cW++ == 0) Wf = (const float*)d_in[i]; else Wb = (const float*)d_in[i]; }
        else if (s == HID * G4)   { if (cU++ == 0) Uf = (const float*)d_in[i]; else Ub = (const float*)d_in[i]; }
        else if (s == G4)         { if (cb++ == 0) bf = (const float*)d_in[i]; else bb = (const float*)d_in[i]; }
    }

    k_init<<<(2 * BATCH * HID + 255) / 256, 256>>>();
    k_transpose<<<(HID * G4 + 255) / 256, 256>>>(Uf, Ub);
    k_gemm<<<dim3((G4 + 63) / 64, ROWS / 64, 2), 256>>>(X, Wf, bf, Wb, bb);
    for (int s = 0; s < SEQ; s++)
        k_step<<<dim3(HID / JT, 2), 256>>>(lengths, s);
    k_final<<<(BATCH * 2 * HID + 255) / 256, 256>>>((float*)d_out);
}

// round 2
// speedup vs baseline: 1.9755x; 1.9755x over previous
#include <cuda_runtime.h>

#define BATCH 64
#define SEQ   512
#define DIM   300
#define HID   600
#define G4    2400            // 4*HID
#define ROWS  (BATCH*SEQ)     // 32768

// persistent-kernel config
#define GRID_P 120
#define NJ     10             // j-units per block
#define NCOL   40             // 4 gates * NJ columns
#define NT     480            // threads (15 warps)
#define KSEG   200            // K split 3 ways: 600/3
#define ZPAD   41             // padded z row

// ---------------- device scratch ----------------
__device__ float g_xw[(size_t)2 * ROWS * G4];   // [dir][row][gatecol]
__device__ float g_UT[2 * G4 * HID];            // [dir][gatecol][k]
__device__ float g_hT[2][2][HID][BATCH];        // [parity][dir][k][b]
__device__ float g_hsum[2 * BATCH * HID];
__device__ unsigned g_cnt;
__device__ unsigned g_rel;

// ---------------- init ----------------
__global__ void k_init() {
    int i = blockIdx.x * blockDim.x + threadIdx.x;
    float* p = &g_hT[0][0][0][0];
    if (i < 2 * 2 * HID * BATCH) p[i] = 0.f;
    if (i == 0) { g_cnt = 0u; g_rel = 0u; }
}

// ---------------- transpose U -> UT ----------------
__global__ void k_transpose(const float* __restrict__ Uf, const float* __restrict__ Ub) {
    int i = blockIdx.x * blockDim.x + threadIdx.x;   // over HID*G4
    if (i >= HID * G4) return;
    int k = i / G4, n = i % G4;
    g_UT[n * HID + k]            = Uf[i];
    g_UT[G4 * HID + n * HID + k] = Ub[i];
}

// ---------------- input GEMM: xw = X @ W + b ----------------
// 128x64 tile, BK=12, 256 threads, 8x4 per thread (FFMA-bound)
#define BM 128
#define BN 64
#define GBK 12
__global__ __launch_bounds__(256) void k_gemm(const float* __restrict__ X,
                       const float* __restrict__ Wf, const float* __restrict__ bf,
                       const float* __restrict__ Wb, const float* __restrict__ bb) {
    int dir = blockIdx.z;
    const float* W    = dir ? Wb : Wf;
    const float* bias = dir ? bb : bf;
    int m0 = blockIdx.y * BM;
    int n0 = blockIdx.x * BN;
    __shared__ __align__(16) float As[GBK][BM];
    __shared__ __align__(16) float Bs[GBK][BN];
    int tid = threadIdx.x;
    int tx = tid & 15, ty = tid >> 4;      // tx: 16 n-groups(4), ty: 16 m-groups(8)
    float acc[8][4] = {};
    for (int k0 = 0; k0 < DIM; k0 += GBK) {
        #pragma unroll
        for (int l = 0; l < (BM * GBK) / 256; ++l) {   // 6
            int idx = tid + l * 256;
            int r = idx / GBK, kk = idx % GBK;
            As[kk][r] = X[(size_t)(m0 + r) * DIM + k0 + kk];
        }
        #pragma unroll
        for (int l = 0; l < (BN * GBK) / 256; ++l) {   // 3
            int idx = tid + l * 256;
            int kk = idx / BN, c = idx & (BN - 1);
            int col = n0 + c;
            Bs[kk][c] = (col < G4) ? W[(size_t)(k0 + kk) * G4 + col] : 0.f;
        }
        __syncthreads();
        #pragma unroll
        for (int kk = 0; kk < GBK; ++kk) {
            float4 a0 = *(const float4*)&As[kk][ty * 8];
            float4 a1 = *(const float4*)&As[kk][ty * 8 + 4];
            float4 b4 = *(const float4*)&Bs[kk][tx * 4];
            float av[8] = {a0.x, a0.y, a0.z, a0.w, a1.x, a1.y, a1.z, a1.w};
            float bv[4] = {b4.x, b4.y, b4.z, b4.w};
            #pragma unroll
            for (int i = 0; i < 8; i++)
                #pragma unroll
                for (int j = 0; j < 4; j++)
                    acc[i][j] += av[i] * bv[j];
        }
        __syncthreads();
    }
    float* outp = g_xw + (size_t)dir * ROWS * G4;
    #pragma unroll
    for (int i = 0; i < 8; i++) {
        int row = m0 + ty * 8 + i;
        #pragma unroll
        for (int j = 0; j < 4; j++) {
            int col = n0 + tx * 4 + j;
            if (col < G4) outp[(size_t)row * G4 + col] = acc[i][j] + bias[col];
        }
    }
}

// ---------------- gate math for one (b, jj) cell ----------------
__device__ __forceinline__ void gate_cell(const float* __restrict__ z_sh,
                                          int b, int jj, int dir, int j0,
                                          int s, int L, int rp,
                                          float& cr, float& hs) {
    float z0 = 0.f, z1 = 0.f, z2 = 0.f, z3 = 0.f;
    #pragma unroll
    for (int p = 0; p < 3; p++) {
        const float* zb = z_sh + (p * 64 + b) * ZPAD;
        z0 += zb[jj];
        z1 += zb[NJ + jj];
        z2 += zb[2 * NJ + jj];
        z3 += zb[3 * NJ + jj];
    }
    bool active = (dir == 0) ? true : (s < L);
    if (!active) return;
    int trow = (dir == 0) ? s : (L - 1 - s);
    const float* xwr = g_xw + ((size_t)dir * ROWS + b * SEQ + trow) * G4 + (j0 + jj);
    float zi = z0 + xwr[0];
    float zf = z1 + xwr[HID];
    float zg = z2 + xwr[2 * HID];
    float zo = z3 + xwr[3 * HID];
    float ig = 1.f / (1.f + __expf(-zi));
    float fg = 1.f / (1.f + __expf(-zf));
    float gg = tanhf(zg);
    float og = 1.f / (1.f + __expf(-zo));
    cr = fg * cr + ig * gg;
    float h = og * tanhf(cr);
    g_hT[rp ^ 1][dir][j0 + jj][b] = h;
    if (dir == 1 || s < L) hs += h;
}

// ---------------- persistent recurrence kernel ----------------
// 120 blocks, each owns NJ=10 j-units of one direction. U slice in SMEM for
// the whole run. One software global barrier per timestep.
__global__ __launch_bounds__(NT, 1) void k_persist(const int* __restrict__ lengths) {
    extern __shared__ __align__(16) float smem[];
    float* u_sh = smem;                    // [HID][NCOL] = 24000 floats
    float* z_sh = smem + HID * NCOL;       // [3][64][ZPAD] = 7872 floats

    int tid = threadIdx.x;
    int bx  = blockIdx.x;
    int dir = (bx >= 60) ? 1 : 0;
    int j0  = (dir ? bx - 60 : bx) * NJ;

    // load this block's U slice into SMEM (once)
    {
        const float* UT = g_UT + (size_t)dir * G4 * HID;
        for (int idx = tid; idx < NCOL * HID; idx += NT) {
            int c = idx / HID, k = idx % HID;
            int gcol = (c / NJ) * HID + j0 + (c % NJ);
            u_sh[k * NCOL + c] = UT[(size_t)gcol * HID + k];
        }
    }

    // compute-thread mapping: 3 K-thirds x (16 b-groups of 4) x (10 c-groups of 4)
    int kh = tid / 160;
    int r  = tid % 160;
    int bb = (r / NJ) * 4;
    int cc = (r % NJ) * 4;

    // gate-cell mapping: cell = jj*64 + b ; thread owns cell tid (always) and
    // cell tid+NT (if tid < 160). c-state and hsum live in registers.
    int b0c  = tid & 63;
    int jj0c = tid / 64;          // 0..7  (tid < 480 -> cell < 512? no: 480/64 = 7.5 -> jj up to 7)
    int b1c  = (tid + NT) & 63;
    int jj1c = (tid + NT) / 64;   // 7..9 for tid<160
    int L0 = lengths[b0c];
    int L1 = (tid < 160) ? lengths[b1c] : 0;
    float cr0 = 0.f, cr1 = 0.f, hs0 = 0.f, hs1 = 0.f;

    __syncthreads();

    for (int s = 0; s < SEQ; s++) {
        int rp = s & 1;
        // ---- partial matvec: z[b, c] += h[b, k] * U[k, c] over this third ----
        const float* hp = &g_hT[rp][dir][kh * KSEG][0] + bb;
        const float* up = u_sh + (kh * KSEG) * NCOL + cc;
        float acc[4][4] = {};
        #pragma unroll 8
        for (int k = 0; k < KSEG; k++) {
            float4 h4 = *(const float4*)hp;  hp += BATCH;
            float4 u4 = *(const float4*)up;  up += NCOL;
            float hv[4] = {h4.x, h4.y, h4.z, h4.w};
            float uv[4] = {u4.x, u4.y, u4.z, u4.w};
            #pragma unroll
            for (int i = 0; i < 4; i++)
                #pragma unroll
                for (int j = 0; j < 4; j++)
                    acc[i][j] += hv[i] * uv[j];
        }
        #pragma unroll
        for (int i = 0; i < 4; i++) {
            float* zp = z_sh + ((kh * 64) + bb + i) * ZPAD + cc;
            zp[0] = acc[i][0]; zp[1] = acc[i][1]; zp[2] = acc[i][2]; zp[3] = acc[i][3];
        }
        __syncthreads();

        // ---- gate math / state update ----
        gate_cell(z_sh, b0c, jj0c, dir, j0, s, L0, rp, cr0, hs0);
        if (tid < 160) gate_cell(z_sh, b1c, jj1c, dir, j0, s, L1, rp, cr1, hs1);
        __syncthreads();

        // ---- global barrier (release h writes, acquire everyone's) ----
        if (tid == 0) {
            __threadfence();
            unsigned a = atomicAdd(&g_cnt, 1u) + 1u;
            if (a == (unsigned)GRID_P * (unsigned)(s + 1)) {
                __threadfence();
                *(volatile unsigned*)&g_rel = (unsigned)(s + 1);
            } else {
                while (*(volatile unsigned*)&g_rel < (unsigned)(s + 1)) {}
            }
            __threadfence();
        }
        __syncthreads();
    }

    // ---- write per-cell hsum to global ----
    g_hsum[dir * BATCH * HID + b0c * HID + j0 + jj0c] = hs0;
    if (tid < 160)
        g_hsum[dir * BATCH * HID + b1c * HID + j0 + jj1c] = hs1;
}

// ---------------- finalize: mean over T ----------------
__global__ void k_final(float* __restrict__ out) {
    int i = blockIdx.x * blockDim.x + threadIdx.x;
    if (i >= BATCH * 2 * HID) return;
    int b = i / (2 * HID), j = i % (2 * HID);
    float v = (j < HID) ? g_hsum[b * HID + j]
                        : g_hsum[BATCH * HID + b * HID + (j - HID)];
    out[i] = v * (1.0f / SEQ);
}

// ---------------- launch ----------------
extern "C" void kernel_launch(void* const* d_in, const int* in_sizes, int n_in,
                              void* d_out, int out_size) {
    const float *X = nullptr, *Wf = nullptr, *Uf = nullptr, *bf = nullptr;
    const float *Wb = nullptr, *Ub = nullptr, *bb = nullptr;
    const int* lengths = nullptr;
    int cW = 0, cU = 0, cb = 0;
    for (int i = 0; i < n_in; i++) {
        int s = in_sizes[i];
        if      (s == BATCH * SEQ * DIM) X = (const float*)d_in[i];
        else if (s == BATCH)             lengths = (const int*)d_in[i];
        else if (s == DIM * G4)   { if (cW++ == 0) Wf = (const float*)d_in[i]; else Wb = (const float*)d_in[i]; }
        else if (s == HID * G4)   { if (cU++ == 0) Uf = (const float*)d_in[i]; else Ub = (const float*)d_in[i]; }
        else if (s == G4)         { if (cb++ == 0) bf = (const float*)d_in[i]; else bb = (const float*)d_in[i]; }
    }

    static const int smem_bytes = (HID * NCOL + 3 * 64 * ZPAD) * 4;   // 127488
    cudaFuncSetAttribute(k_persist, cudaFuncAttributeMaxDynamicSharedMemorySize, smem_bytes);

    k_init<<<(2 * 2 * HID * BATCH + 255) / 256, 256>>>();
    k_transpose<<<(HID * G4 + 255) / 256, 256>>>(Uf, Ub);
    k_gemm<<<dim3((G4 + BN - 1) / BN, ROWS / BM, 2), 256>>>(X, Wf, bf, Wb, bb);
    k_persist<<<GRID_P, NT, smem_bytes>>>(lengths);
    k_final<<<(BATCH * 2 * HID + 255) / 256, 256>>>((float*)d_out);
}

// round 3
// speedup vs baseline: 2.2289x; 1.1283x over previous
#include <cuda_runtime.h>

#define BATCH 64
#define SEQ   512
#define DIM   300
#define HID   600
#define G4    2400            // 4*HID
#define ROWS  (BATCH*SEQ)     // 32768

// persistent-kernel config
#define GRID_P 120
#define NJ     10             // j-units per block
#define NCOL   40             // 4 gates * NJ columns
#define NT     480            // threads (15 warps)
#define KSPLIT 6
#define KSEG   100            // 600 / KSPLIT
#define ZPAD   42             // padded z row (8B-aligned rows)

typedef unsigned long long u64;

// ---------------- packed f32x2 helpers ----------------
__device__ __forceinline__ void ffma2(u64& d, u64 a, u64 b) {
    asm("fma.rn.f32x2 %0, %1, %2, %0;" : "+l"(d) : "l"(a), "l"(b));
}
__device__ __forceinline__ u64 pack2(float lo, float hi) {
    u64 r; asm("mov.b64 %0, {%1, %2};" : "=l"(r) : "f"(lo), "f"(hi)); return r;
}
__device__ __forceinline__ void unpack2(u64 v, float& lo, float& hi) {
    asm("mov.b64 {%0, %1}, %2;" : "=f"(lo), "=f"(hi) : "l"(v));
}

// ---------------- device scratch ----------------
__device__ float g_xw[(size_t)2 * ROWS * G4];   // [dir][row][gatecol]
__device__ float g_UT[2 * G4 * HID];            // [dir][gatecol][k]
__device__ float g_hT[2][2][HID][BATCH];        // [parity][dir][k][b]
__device__ float g_hsum[2 * BATCH * HID];
__device__ unsigned g_cnt;
__device__ unsigned g_rel;

// ---------------- init ----------------
__global__ void k_init() {
    int i = blockIdx.x * blockDim.x + threadIdx.x;
    float* p = &g_hT[0][0][0][0];
    if (i < 2 * 2 * HID * BATCH) p[i] = 0.f;
    if (i == 0) { g_cnt = 0u; g_rel = 0u; }
}

// ---------------- transpose U -> UT ----------------
__global__ void k_transpose(const float* __restrict__ Uf, const float* __restrict__ Ub) {
    int i = blockIdx.x * blockDim.x + threadIdx.x;   // over HID*G4
    if (i >= HID * G4) return;
    int k = i / G4, n = i % G4;
    g_UT[n * HID + k]            = Uf[i];
    g_UT[G4 * HID + n * HID + k] = Ub[i];
}

// ---------------- input GEMM: xw = X @ W + b (FFMA2) ----------------
#define BM 128
#define BN 64
#define GBK 12
__global__ __launch_bounds__(256) void k_gemm(const float* __restrict__ X,
                       const float* __restrict__ Wf, const float* __restrict__ bf,
                       const float* __restrict__ Wb, const float* __restrict__ bb) {
    int dir = blockIdx.z;
    const float* W    = dir ? Wb : Wf;
    const float* bias = dir ? bb : bf;
    int m0 = blockIdx.y * BM;
    int n0 = blockIdx.x * BN;
    __shared__ __align__(16) float As[GBK][BM];
    __shared__ __align__(16) float Bs[GBK][BN];
    int tid = threadIdx.x;
    int tx = tid & 15, ty = tid >> 4;      // tx: 16 n-groups(4), ty: 16 m-groups(8)
    u64 acc2[4][4] = {};                   // [m-pair][n]
    for (int k0 = 0; k0 < DIM; k0 += GBK) {
        #pragma unroll
        for (int l = 0; l < (BM * GBK) / 256; ++l) {   // 6
            int idx = tid + l * 256;
            int r = idx / GBK, kk = idx % GBK;
            As[kk][r] = X[(size_t)(m0 + r) * DIM + k0 + kk];
        }
        #pragma unroll
        for (int l = 0; l < (BN * GBK) / 256; ++l) {   // 3
            int idx = tid + l * 256;
            int kk = idx / BN, c = idx & (BN - 1);
            int col = n0 + c;
            Bs[kk][c] = (col < G4) ? W[(size_t)(k0 + kk) * G4 + col] : 0.f;
        }
        __syncthreads();
        #pragma unroll
        for (int kk = 0; kk < GBK; ++kk) {
            float4 a0 = *(const float4*)&As[kk][ty * 8];
            float4 a1 = *(const float4*)&As[kk][ty * 8 + 4];
            float4 b4 = *(const float4*)&Bs[kk][tx * 4];
            u64 ap[4] = {pack2(a0.x, a0.y), pack2(a0.z, a0.w),
                         pack2(a1.x, a1.y), pack2(a1.z, a1.w)};
            u64 bp[4] = {pack2(b4.x, b4.x), pack2(b4.y, b4.y),
                         pack2(b4.z, b4.z), pack2(b4.w, b4.w)};
            #pragma unroll
            for (int i = 0; i < 4; i++)
                #pragma unroll
                for (int j = 0; j < 4; j++)
                    ffma2(acc2[i][j], ap[i], bp[j]);
        }
        __syncthreads();
    }
    float* outp = g_xw + (size_t)dir * ROWS * G4;
    #pragma unroll
    for (int i = 0; i < 4; i++) {
        int row = m0 + ty * 8 + 2 * i;
        #pragma unroll
        for (int j = 0; j < 4; j++) {
            int col = n0 + tx * 4 + j;
            if (col < G4) {
                float lo, hi; unpack2(acc2[i][j], lo, hi);
                float bv = bias[col];
                outp[(size_t)row * G4 + col]       = lo + bv;
                outp[(size_t)(row + 1) * G4 + col] = hi + bv;
            }
        }
    }
}

// ---------------- xw prefetch for one (b, jj) cell ----------------
__device__ __forceinline__ void load_xw4(float* px, int s, int b, int jj,
                                         int dir, int j0, int L) {
    bool active = (dir == 0) ? (s < SEQ) : (s < L);
    if (!active) return;
    int trow = (dir == 0) ? s : (L - 1 - s);
    const float* xwr = g_xw + ((size_t)dir * ROWS + b * SEQ + trow) * G4 + (j0 + jj);
    px[0] = xwr[0];
    px[1] = xwr[HID];
    px[2] = xwr[2 * HID];
    px[3] = xwr[3 * HID];
}

// ---------------- gate math for one (b, jj) cell ----------------
__device__ __forceinline__ void gate_cell(const float* __restrict__ z_sh,
                                          const float* __restrict__ px,
                                          int b, int jj, int dir, int j0,
                                          int s, int L, int rp,
                                          float& cr, float& hs) {
    float z0 = 0.f, z1 = 0.f, z2 = 0.f, z3 = 0.f;
    #pragma unroll
    for (int p = 0; p < KSPLIT; p++) {
        const float* zb = z_sh + (p * 64 + b) * ZPAD;
        z0 += zb[jj];
        z1 += zb[NJ + jj];
        z2 += zb[2 * NJ + jj];
        z3 += zb[3 * NJ + jj];
    }
    bool active = (dir == 0) ? true : (s < L);
    if (!active) return;
    float zi = z0 + px[0];
    float zf = z1 + px[1];
    float zg = z2 + px[2];
    float zo = z3 + px[3];
    float ig = 1.f / (1.f + __expf(-zi));
    float fg = 1.f / (1.f + __expf(-zf));
    float gg = tanhf(zg);
    float og = 1.f / (1.f + __expf(-zo));
    cr = fg * cr + ig * gg;
    float h = og * tanhf(cr);
    g_hT[rp ^ 1][dir][j0 + jj][b] = h;
    if (dir == 1 || s < L) hs += h;
}

// ---------------- persistent recurrence kernel ----------------
__global__ __launch_bounds__(NT, 1) void k_persist(const int* __restrict__ lengths) {
    extern __shared__ __align__(16) float smem[];
    float* u_sh = smem;                    // [HID][NCOL] = 24000 floats
    float* z_sh = smem + HID * NCOL;       // [KSPLIT][64][ZPAD]

    int tid = threadIdx.x;
    int bx  = blockIdx.x;
    int dir = (bx >= 60) ? 1 : 0;
    int j0  = (dir ? bx - 60 : bx) * NJ;

    // load this block's U slice into SMEM (once)
    {
        const float* UT = g_UT + (size_t)dir * G4 * HID;
        for (int idx = tid; idx < NCOL * HID; idx += NT) {
            int c = idx / HID, k = idx % HID;
            int gcol = (c / NJ) * HID + j0 + (c % NJ);
            u_sh[k * NCOL + c] = UT[(size_t)gcol * HID + k];
        }
    }

    // compute mapping: KSPLIT k-segs x 8 b-groups(8) x 10 c-groups(4)
    int kh = tid / 80;
    int r  = tid % 80;
    int bb = (r / 10) * 8;
    int cc = (r % 10) * 4;

    // gate-cell mapping: cell = jj*64 + b
    int b0c  = tid & 63;
    int jj0c = tid / 64;          // 0..7
    int b1c  = (tid + NT) & 63;
    int jj1c = (tid + NT) / 64;   // 7..9 for tid<160
    int L0 = lengths[b0c];
    int L1 = (tid < 160) ? lengths[b1c] : 0;
    float cr0 = 0.f, cr1 = 0.f, hs0 = 0.f, hs1 = 0.f;

    float px0[4], px1[4], nx0[4], nx1[4];
    load_xw4(px0, 0, b0c, jj0c, dir, j0, L0);
    if (tid < 160) load_xw4(px1, 0, b1c, jj1c, dir, j0, L1);

    __syncthreads();

    for (int s = 0; s < SEQ; s++) {
        int rp = s & 1;
        // ---- partial matvec: z[b, c] += h[b, k] * U[k, c] over this k-seg ----
        const float* hp = &g_hT[rp][dir][kh * KSEG][0] + bb;
        const float* up = u_sh + (kh * KSEG) * NCOL + cc;
        u64 acc2[4][4] = {};
        #pragma unroll 4
        for (int k = 0; k < KSEG; k++) {
            float4 ha = *(const float4*)hp;
            float4 hb = *(const float4*)(hp + 4);
            hp += BATCH;
            float4 u4 = *(const float4*)up;
            up += NCOL;
            u64 hpair[4] = {pack2(ha.x, ha.y), pack2(ha.z, ha.w),
                            pack2(hb.x, hb.y), pack2(hb.z, hb.w)};
            u64 ub[4] = {pack2(u4.x, u4.x), pack2(u4.y, u4.y),
                         pack2(u4.z, u4.z), pack2(u4.w, u4.w)};
            #pragma unroll
            for (int i = 0; i < 4; i++)
                #pragma unroll
                for (int j = 0; j < 4; j++)
                    ffma2(acc2[i][j], hpair[i], ub[j]);
        }
        #pragma unroll
        for (int i = 0; i < 4; i++) {
            float* zr0 = z_sh + ((kh * 64) + bb + 2 * i) * ZPAD + cc;
            float* zr1 = zr0 + ZPAD;
            #pragma unroll
            for (int j = 0; j < 4; j++) {
                float lo, hi; unpack2(acc2[i][j], lo, hi);
                zr0[j] = lo; zr1[j] = hi;
            }
        }

        // ---- prefetch next step's xw (hides DRAM latency under gate/sync) ----
        load_xw4(nx0, s + 1, b0c, jj0c, dir, j0, L0);
        if (tid < 160) load_xw4(nx1, s + 1, b1c, jj1c, dir, j0, L1);

        __syncthreads();

        // ---- gate math / state update ----
        gate_cell(z_sh, px0, b0c, jj0c, dir, j0, s, L0, rp, cr0, hs0);
        if (tid < 160) gate_cell(z_sh, px1, b1c, jj1c, dir, j0, s, L1, rp, cr1, hs1);
        #pragma unroll
        for (int q = 0; q < 4; q++) { px0[q] = nx0[q]; px1[q] = nx1[q]; }
        __syncthreads();

        // ---- global barrier ----
        if (tid == 0) {
            __threadfence();
            unsigned a = atomicAdd(&g_cnt, 1u) + 1u;
            if (a == (unsigned)GRID_P * (unsigned)(s + 1)) {
                __threadfence();
                *(volatile unsigned*)&g_rel = (unsigned)(s + 1);
            } else {
                while (*(volatile unsigned*)&g_rel < (unsigned)(s + 1)) {}
            }
            __threadfence();
        }
        __syncthreads();
    }

    // ---- write per-cell hsum to global ----
    g_hsum[dir * BATCH * HID + b0c * HID + j0 + jj0c] = hs0;
    if (tid < 160)
        g_hsum[dir * BATCH * HID + b1c * HID + j0 + jj1c] = hs1;
}

// ---------------- finalize: mean over T ----------------
__global__ void k_final(float* __restrict__ out) {
    int i = blockIdx.x * blockDim.x + threadIdx.x;
    if (i >= BATCH * 2 * HID) return;
    int b = i / (2 * HID), j = i % (2 * HID);
    float v = (j < HID) ? g_hsum[b * HID + j]
                        : g_hsum[BATCH * HID + b * HID + (j - HID)];
    out[i] = v * (1.0f / SEQ);
}

// ---------------- launch ----------------
extern "C" void kernel_launch(void* const* d_in, const int* in_sizes, int n_in,
                              void* d_out, int out_size) {
    const float *X = nullptr, *Wf = nullptr, *Uf = nullptr, *bf = nullptr;
    const float *Wb = nullptr, *Ub = nullptr, *bb = nullptr;
    const int* lengths = nullptr;
    int cW = 0, cU = 0, cb = 0;
    for (int i = 0; i < n_in; i++) {
        int s = in_sizes[i];
        if      (s == BATCH * SEQ * DIM) X = (const float*)d_in[i];
        else if (s == BATCH)             lengths = (const int*)d_in[i];
        else if (s == DIM * G4)   { if (cW++ == 0) Wf = (const float*)d_in[i]; else Wb = (const float*)d_in[i]; }
        else if (s == HID * G4)   { if (cU++ == 0) Uf = (const float*)d_in[i]; else Ub = (const float*)d_in[i]; }
        else if (s == G4)         { if (cb++ == 0) bf = (const float*)d_in[i]; else bb = (const float*)d_in[i]; }
    }

    static const int smem_bytes = (HID * NCOL + KSPLIT * 64 * ZPAD) * 4;   // 160512
    cudaFuncSetAttribute(k_persist, cudaFuncAttributeMaxDynamicSharedMemorySize, smem_bytes);

    k_init<<<(2 * 2 * HID * BATCH + 255) / 256, 256>>>();
    k_transpose<<<(HID * G4 + 255) / 256, 256>>>(Uf, Ub);
    k_gemm<<<dim3((G4 + BN - 1) / BN, ROWS / BM, 2), 256>>>(X, Wf, bf, Wb, bb);
    k_persist<<<GRID_P, NT, smem_bytes>>>(lengths);
    k_final<<<(BATCH * 2 * HID + 255) / 256, 256>>>((float*)d_out);
}